// round 5
// baseline (speedup 1.0000x reference)
#include <cuda_runtime.h>

// Problem constants
#define N_TOT 8192
#define F_DIM 128
#define FP    (F_DIM / 2)          // 64 f-pairs
#define NFP   (N_TOT * FP)         // 524,288 threads, each handles (f, f+1)

// out[n,a,b,f,uv] = 0.75*(x[n,a,f,u]*y[n,b,f,v] + x[n,b,f,u]*y[n,a,f,v])
//                 - 0.5*z[n,f,uv]*(a==b)
// x: [N,3,F,2]  y: [N,3,F,2]  z: [N,F,4]  out: [N,3,3,F,4]
//
// Each thread processes two adjacent f (one f-pair):
//  - x[n,a,2fp..2fp+1,:] = 4 contiguous floats -> one float4 load (LDG.128)
//  - all 8 loads front-batched for max MLP; 18 float4 stores, warp-contiguous
//    1 KB segments per (a,b) tile for better DRAM write batching.
__global__ __launch_bounds__(256) void tp_block2_kernel(
    const float4* __restrict__ x,   // viewed as [N,3,FP] float4
    const float4* __restrict__ y,   // viewed as [N,3,FP] float4
    const float4* __restrict__ z,   // viewed as [N,F] float4
    float4* __restrict__ out)       // viewed as [N,3,3,F] float4
{
    int idx = blockIdx.x * blockDim.x + threadIdx.x;
    if (idx >= NFP) return;
    int n  = idx / FP;
    int fp = idx - n * FP;          // f-pair index; f0 = 2*fp, f1 = 2*fp+1

    // Front-batch all 8 LDG.128 loads.
    int base = (n * 3) * FP + fp;   // float4 index of x[n,0,2fp..2fp+1,:]
    float4 xa[3], yb[3];
    xa[0] = x[base];
    xa[1] = x[base + FP];
    xa[2] = x[base + 2 * FP];
    yb[0] = y[base];
    yb[1] = y[base + FP];
    yb[2] = y[base + 2 * FP];
    int zbase = n * F_DIM + 2 * fp;
    float4 z0 = z[zbase];
    float4 z1 = z[zbase + 1];

    const float c1 = 0.75f;         // NORM_112
    const float c2 = 0.5f;          // 0.75 * 2/3

    // Pre-scale z (diagonal term).
    float4 zc0, zc1;
    zc0.x = c2 * z0.x; zc0.y = c2 * z0.y; zc0.z = c2 * z0.z; zc0.w = c2 * z0.w;
    zc1.x = c2 * z1.x; zc1.y = c2 * z1.y; zc1.z = c2 * z1.z; zc1.w = c2 * z1.w;

    // xa[a] = (f0.u0, f0.u1, f1.u0, f1.u1); same layout for yb.
    int obase = (n * 9) * F_DIM + 2 * fp;   // float4 index of out[n,0,0,2fp]
#pragma unroll
    for (int a = 0; a < 3; a++) {
#pragma unroll
        for (int b = 0; b < 3; b++) {
            float4 v0, v1;
            // f0: uses .x/.y halves
            v0.x = c1 * (xa[a].x * yb[b].x + xa[b].x * yb[a].x);
            v0.y = c1 * (xa[a].x * yb[b].y + xa[b].x * yb[a].y);
            v0.z = c1 * (xa[a].y * yb[b].x + xa[b].y * yb[a].x);
            v0.w = c1 * (xa[a].y * yb[b].y + xa[b].y * yb[a].y);
            // f1: uses .z/.w halves
            v1.x = c1 * (xa[a].z * yb[b].z + xa[b].z * yb[a].z);
            v1.y = c1 * (xa[a].z * yb[b].w + xa[b].z * yb[a].w);
            v1.z = c1 * (xa[a].w * yb[b].z + xa[b].w * yb[a].z);
            v1.w = c1 * (xa[a].w * yb[b].w + xa[b].w * yb[a].w);
            if (a == b) {
                v0.x -= zc0.x; v0.y -= zc0.y; v0.z -= zc0.z; v0.w -= zc0.w;
                v1.x -= zc1.x; v1.y -= zc1.y; v1.z -= zc1.z; v1.w -= zc1.w;
            }
            int o = obase + (a * 3 + b) * F_DIM;
            out[o]     = v0;
            out[o + 1] = v1;
        }
    }
}

extern "C" void kernel_launch(void* const* d_in, const int* in_sizes, int n_in,
                              void* d_out, int out_size) {
    const float4* x = (const float4*)d_in[0];
    const float4* y = (const float4*)d_in[1];
    const float4* z = (const float4*)d_in[2];
    // d_in[3] is eye (identity) — value known, not needed.
    float4* out = (float4*)d_out;

    const int threads = 256;
    const int blocks = (NFP + threads - 1) / threads;
    tp_block2_kernel<<<blocks, threads>>>(x, y, z, out);
}

// round 6
// speedup vs baseline: 1.6498x; 1.6498x over previous
#include <cuda_runtime.h>

// Problem constants
#define N_TOT 8192
#define F_DIM 128
#define FP    (F_DIM / 2)          // 64 f-pairs
#define NFP   (N_TOT * FP)         // 524,288 threads, each handles (f, f+1)

// out[n,a,b,f,uv] = 0.75*(x[n,a,f,u]*y[n,b,f,v] + x[n,b,f,u]*y[n,a,f,v])
//                 - 0.5*z[n,f,uv]*(a==b)
// x: [N,3,F,2]  y: [N,3,F,2]  z: [N,F,4]  out: [N,3,3,F,4]
//
// Each thread handles two adjacent f, and every output tile is written as ONE
// 256-bit store (st.global.v8.f32, sm_100+): 32 contiguous bytes per thread,
// so each warp store is a single fully-dense 1 KB transaction. This fixes the
// 50% store-sector density that sank the plain f-pair variant, while keeping
// LDG.128 input loads and half the instruction count of the 1-f kernel.

__device__ __forceinline__ void stg256(float4* p, float4 v0, float4 v1) {
    asm volatile(
        "st.global.v8.f32 [%0], {%1, %2, %3, %4, %5, %6, %7, %8};"
        :: "l"(p),
           "f"(v0.x), "f"(v0.y), "f"(v0.z), "f"(v0.w),
           "f"(v1.x), "f"(v1.y), "f"(v1.z), "f"(v1.w)
        : "memory");
}

__device__ __forceinline__ void ldg256(const float4* p, float4& v0, float4& v1) {
    asm volatile(
        "ld.global.nc.v8.f32 {%0, %1, %2, %3, %4, %5, %6, %7}, [%8];"
        : "=f"(v0.x), "=f"(v0.y), "=f"(v0.z), "=f"(v0.w),
          "=f"(v1.x), "=f"(v1.y), "=f"(v1.z), "=f"(v1.w)
        : "l"(p));
}

__global__ __launch_bounds__(128) void tp_block2_kernel(
    const float4* __restrict__ x,   // viewed as [N,3,FP] float4
    const float4* __restrict__ y,   // viewed as [N,3,FP] float4
    const float4* __restrict__ z,   // viewed as [N,F] float4
    float4* __restrict__ out)       // viewed as [N,3,3,F] float4
{
    int idx = blockIdx.x * blockDim.x + threadIdx.x;
    if (idx >= NFP) return;
    int n  = idx / FP;
    int fp = idx - n * FP;          // f-pair index; f0 = 2*fp, f1 = 2*fp+1

    // Front-batch all loads: 6x LDG.128 + 1x LDG.256.
    int base = (n * 3) * FP + fp;   // float4 index of x[n,0,2fp..2fp+1,:]
    float4 xa[3], yb[3];
    xa[0] = x[base];
    xa[1] = x[base + FP];
    xa[2] = x[base + 2 * FP];
    yb[0] = y[base];
    yb[1] = y[base + FP];
    yb[2] = y[base + 2 * FP];
    float4 z0, z1;
    ldg256(&z[n * F_DIM + 2 * fp], z0, z1);

    const float c1 = 0.75f;         // NORM_112
    const float c2 = 0.5f;          // 0.75 * 2/3

    // Pre-scale z (diagonal term).
    float4 zc0, zc1;
    zc0.x = c2 * z0.x; zc0.y = c2 * z0.y; zc0.z = c2 * z0.z; zc0.w = c2 * z0.w;
    zc1.x = c2 * z1.x; zc1.y = c2 * z1.y; zc1.z = c2 * z1.z; zc1.w = c2 * z1.w;

    // xa[a] = (f0.u0, f0.u1, f1.u0, f1.u1); same layout for yb.
    int obase = (n * 9) * F_DIM + 2 * fp;   // float4 index of out[n,0,0,2fp]
#pragma unroll
    for (int a = 0; a < 3; a++) {
#pragma unroll
        for (int b = 0; b < 3; b++) {
            float4 v0, v1;
            // f0: uses .x/.y halves
            v0.x = c1 * (xa[a].x * yb[b].x + xa[b].x * yb[a].x);
            v0.y = c1 * (xa[a].x * yb[b].y + xa[b].x * yb[a].y);
            v0.z = c1 * (xa[a].y * yb[b].x + xa[b].y * yb[a].x);
            v0.w = c1 * (xa[a].y * yb[b].y + xa[b].y * yb[a].y);
            // f1: uses .z/.w halves
            v1.x = c1 * (xa[a].z * yb[b].z + xa[b].z * yb[a].z);
            v1.y = c1 * (xa[a].z * yb[b].w + xa[b].z * yb[a].w);
            v1.z = c1 * (xa[a].w * yb[b].z + xa[b].w * yb[a].z);
            v1.w = c1 * (xa[a].w * yb[b].w + xa[b].w * yb[a].w);
            if (a == b) {
                v0.x -= zc0.x; v0.y -= zc0.y; v0.z -= zc0.z; v0.w -= zc0.w;
                v1.x -= zc1.x; v1.y -= zc1.y; v1.z -= zc1.z; v1.w -= zc1.w;
            }
            stg256(&out[obase + (a * 3 + b) * F_DIM], v0, v1);
        }
    }
}

extern "C" void kernel_launch(void* const* d_in, const int* in_sizes, int n_in,
                              void* d_out, int out_size) {
    const float4* x = (const float4*)d_in[0];
    const float4* y = (const float4*)d_in[1];
    const float4* z = (const float4*)d_in[2];
    // d_in[3] is eye (identity) — value known, not needed.
    float4* out = (float4*)d_out;

    const int threads = 128;
    const int blocks = (NFP + threads - 1) / threads;
    tp_block2_kernel<<<blocks, threads>>>(x, y, z, out);
}